// round 1
// baseline (speedup 1.0000x reference)
#include <cuda_runtime.h>
#include <cstdint>

// ============================================================================
// AddNoise: out[b,j] = (sigma_j + 0.1*normal(k4)[b,j]) * x[b,j]
//                      + (mu_j + uniform(k3, -0.05, 0.05)[b,j])
// mu_j    = uniform(k1, (N,), -0.1, 0.1)
// sigma_j = uniform(k2, (N,), 1.0, 2.0)
// k1..k4 = jax.random.split(key(42), 4)   [threefry, partitionable/foldlike]
// ============================================================================

#define NCOLS 8192
#define NROWS 4096
#define NELEM (NCOLS * NROWS)   // 33554432 = 2^25

struct KeyPair { unsigned a, b; };

constexpr unsigned rotl_c(unsigned x, int d) { return (x << d) | (x >> (32 - d)); }

// Full threefry2x32, constexpr (for compile-time key derivation).
constexpr KeyPair tf_pair_c(unsigned k0, unsigned k1, unsigned x0, unsigned x1) {
    unsigned ks0 = k0, ks1 = k1, ks2 = k0 ^ k1 ^ 0x1BD11BDAu;
    x0 += ks0; x1 += ks1;
    const int rotA[4] = {13, 15, 26, 6};
    const int rotB[4] = {17, 29, 16, 24};
    unsigned ks[3] = {ks0, ks1, ks2};
    for (int i = 0; i < 5; ++i) {
        const int* rot = (i & 1) ? rotB : rotA;
        for (int r = 0; r < 4; ++r) {
            x0 += x1;
            x1 = rotl_c(x1, rot[r]);
            x1 ^= x0;
        }
        x0 += ks[(i + 1) % 3];
        x1 += ks[(i + 2) % 3] + (unsigned)(i + 1);
    }
    return {x0, x1};
}

// jax.random.key(42) -> (0, 42); split(key, 4) foldlike:
//   k_i = threefry2x32((0,42), (0, i))
constexpr KeyPair K1 = tf_pair_c(0u, 42u, 0u, 0u);
constexpr KeyPair K2 = tf_pair_c(0u, 42u, 0u, 1u);
constexpr KeyPair K3 = tf_pair_c(0u, 42u, 0u, 2u);
constexpr KeyPair K4 = tf_pair_c(0u, 42u, 0u, 3u);

// Device threefry2x32 with compile-time keys; counter hi word is always 0
// (all sizes < 2^32). Returns o0 ^ o1 (partitionable 32-bit random bits).
template <unsigned KA, unsigned KB>
__device__ __forceinline__ unsigned tf_xor(unsigned ctr) {
    constexpr unsigned KC = KA ^ KB ^ 0x1BD11BDAu;
    unsigned x0 = KA;           // 0 + ks0
    unsigned x1 = ctr + KB;     // ctr + ks1
#define TF_RND(r) { x0 += x1; x1 = __funnelshift_l(x1, x1, (r)); x1 ^= x0; }
    TF_RND(13) TF_RND(15) TF_RND(26) TF_RND(6)
    x0 += KB; x1 += KC + 1u;
    TF_RND(17) TF_RND(29) TF_RND(16) TF_RND(24)
    x0 += KC; x1 += KA + 2u;
    TF_RND(13) TF_RND(15) TF_RND(26) TF_RND(6)
    x0 += KA; x1 += KB + 3u;
    TF_RND(17) TF_RND(29) TF_RND(16) TF_RND(24)
    x0 += KB; x1 += KC + 4u;
    TF_RND(13) TF_RND(15) TF_RND(26) TF_RND(6)
    x0 += KC; x1 += KA + 5u;
#undef TF_RND
    return x0 ^ x1;
}

// bits -> [0, 1) exactly like jax: bitcast((bits>>9)|0x3f800000) - 1.0
__device__ __forceinline__ float u01(unsigned bits) {
    return __uint_as_float((bits >> 9) | 0x3f800000u) - 1.0f;
}

// Per-column parameters (mu_j, sigma_j), computed each launch.
__device__ float2 g_cols[NCOLS];

__global__ void col_kernel() {
    unsigned j = blockIdx.x * blockDim.x + threadIdx.x;  // 8192 threads exactly
    float fmu = u01(tf_xor<K1.a, K1.b>(j));
    float mu  = fmaxf(-0.1f, fmaf(fmu, 0.2f, -0.1f));
    float fsg = u01(tf_xor<K2.a, K2.b>(j));
    float sg  = fmaxf(1.0f, fmaf(fsg, 1.0f, 1.0f));
    g_cols[j] = make_float2(mu, sg);
}

__global__ void __launch_bounds__(256) noise_kernel(const float4* __restrict__ x,
                                                    float4* __restrict__ out) {
    unsigned t  = blockIdx.x * blockDim.x + threadIdx.x;
    unsigned e0 = t << 2;                 // first of 4 consecutive elements
    unsigned j0 = e0 & (NCOLS - 1);       // column (N is power of two)

    float4 xv = x[t];

    const float4* cp = reinterpret_cast<const float4*>(g_cols);
    float4 c01 = cp[(j0 >> 1) + 0];       // {mu0, sg0, mu1, sg1}
    float4 c23 = cp[(j0 >> 1) + 1];       // {mu2, sg2, mu3, sg3}

    float mu[4]  = {c01.x, c01.z, c23.x, c23.z};
    float sg[4]  = {c01.y, c01.w, c23.y, c23.w};
    float xs[4]  = {xv.x, xv.y, xv.z, xv.w};
    float res[4];

    constexpr float LO = -0.99999994039535522461f;  // nextafterf(-1, 0)
    constexpr float SQRT2 = 1.4142135381698608f;    // float32(sqrt(2))

#pragma unroll
    for (int i = 0; i < 4; ++i) {
        unsigned e = e0 + (unsigned)i;

        // mMat noise: uniform(k3, -0.05, 0.05)
        float f3 = u01(tf_xor<K3.a, K3.b>(e));
        float nm = fmaxf(-0.05f, fmaf(f3, 0.1f, -0.05f));

        // sMat noise: 0.1 * normal(k4) ; normal = sqrt2 * erfinv(uniform(LO, 1))
        float f4 = u01(tf_xor<K4.a, K4.b>(e));
        float u  = fmaxf(LO, fmaf(f4, 2.0f, LO));   // (1 - LO) rounds to 2.0f
        float nr = SQRT2 * erfinvf(u);

        float s = fmaf(0.1f, nr, sg[i]);
        float m = mu[i] + nm;
        res[i]  = fmaf(s, xs[i], m);
    }

    out[t] = make_float4(res[0], res[1], res[2], res[3]);
}

extern "C" void kernel_launch(void* const* d_in, const int* in_sizes, int n_in,
                              void* d_out, int out_size) {
    const float* x = (const float*)d_in[0];
    float* out = (float*)d_out;

    col_kernel<<<NCOLS / 256, 256>>>();
    noise_kernel<<<(NELEM / 4) / 256, 256>>>(
        reinterpret_cast<const float4*>(x), reinterpret_cast<float4*>(out));
}